// round 5
// baseline (speedup 1.0000x reference)
#include <cuda_runtime.h>
#include <cstdint>

// Problem constants
#define BATCH 32
#define NPTS  65536          // N
#define LOGN  16
#define GRIDW 128            // S / D1 = 384 / 3
#define OUT_ELEMS (BATCH * GRIDW * GRIDW * 3)   // 1,572,864 floats

// Scratch: packed per-point lattice coords (gq0 lo16, gq1 hi16)
__device__ int g_scratch[BATCH * NPTS];
// Per-batch key minima for dims 0,1
__device__ int g_offmin[BATCH * 2];

// Separately-rounded dot3, left-associated ascending k (XLA loop-emitter order,
// NO fma contraction): fl(fl(fl(a0*b0) + fl(a1*b1)) + fl(a2*b2))
__device__ __forceinline__ float dot3_rn(float a0, float a1, float a2,
                                         float b0, float b1, float b2) {
    float s = __fmul_rn(a0, b0);
    s = __fadd_rn(s, __fmul_rn(a1, b1));
    s = __fadd_rn(s, __fmul_rn(a2, b2));
    return s;
}

// XLA:GPU-style f32 division: div.full.f32 (fast, <=2ulp, not IEEE-rounded)
__device__ __forceinline__ float fdiv_full(float a, float b) {
    float r;
    asm("div.full.f32 %0, %1, %2;" : "=f"(r) : "f"(a), "f"(b));
    return r;
}

// ---------------------------------------------------------------------------
// Kernel Z: zero the output, init the min buffers
// ---------------------------------------------------------------------------
__global__ void zero_kernel(float4* __restrict__ out) {
    int i = blockIdx.x * blockDim.x + threadIdx.x;
    if (i < OUT_ELEMS / 4) out[i] = make_float4(0.f, 0.f, 0.f, 0.f);
    if (blockIdx.x == 0 && threadIdx.x < BATCH * 2) g_offmin[threadIdx.x] = 0x7FFFFFFF;
}

// ---------------------------------------------------------------------------
// Kernel A: per-point lattice coords + global min reduction
// grid = BATCH * 256 blocks, 256 threads (one thread per point)
// ---------------------------------------------------------------------------
__global__ void __launch_bounds__(256) keys_kernel(const float* __restrict__ pc1,
                                                   const float* __restrict__ tmat) {
    const int b = blockIdx.x >> 8;
    const int n = ((blockIdx.x & 255) << 8) | threadIdx.x;

    const float* pc = pc1 + ((size_t)b * 3) * NPTS + n;
    const float p0 = pc[0];
    const float p1 = pc[NPTS];
    const float p2 = pc[2 * NPTS];

    const float* tm = tmat + b * 9;
    // elevated = trans_mat @ pc, separately-rounded mul/add (no FMA)
    const float e0 = dot3_rn(tm[0], tm[1], tm[2], p0, p1, p2);
    const float e1 = dot3_rn(tm[3], tm[4], tm[5], p0, p1, p2);
    const float e2 = dot3_rn(tm[6], tm[7], tm[8], p0, p1, p2);

    // greedy = round(e/3)*3.  Division via div.full.f32 (XLA:GPU lowering);
    // rintf = round-half-even (matches jnp.round).
    const float q0 = rintf(fdiv_full(e0, 3.0f));
    const float q1 = rintf(fdiv_full(e1, 3.0f));
    const float q2 = rintf(fdiv_full(e2, 3.0f));
    const float m0 = __fadd_rn(e0, -__fmul_rn(3.0f, q0));  // 3*q exact; single rounding
    const float m1 = __fadd_rn(e1, -__fmul_rn(3.0f, q1));
    const float m2 = __fadd_rn(e2, -__fmul_rn(3.0f, q2));

    // rank = stable descending rank of emg
    int r0 = (int)(m1 > m0) + (int)(m2 > m0);
    int r1 = (int)(m0 >= m1) + (int)(m2 > m1);

    int gq0 = (int)q0, gq1 = (int)q1, gq2 = (int)q2;
    const int rs = gq0 + gq1 + gq2;            // == sum(greedy)/3 exactly
    const int s  = (rs > 0) ? -1 : ((rs < 0) ? 1 : 0);

    // canonical simplex adjustment (only dims 0,1 are used downstream)
    const bool c0 = (rs > 0 && r0 >= 3 - rs) || (rs < 0 && r0 < -rs);
    const bool c1 = (rs > 0 && r1 >= 3 - rs) || (rs < 0 && r1 < -rs);
    gq0 += c0 ? s : 0;  r0 += (c0 ? 3 * s : 0) + rs;
    gq1 += c1 ? s : 0;  r1 += (c1 ? 3 * s : 0) + rs;

    // clamp rank for CANONICAL gather (JAX clamps OOB gather indices)
    const int rc0 = min(max(r0, 0), 2);
    const int rc1 = min(max(r1, 0), 2);

    // per-point min over k of key = 3*gq - rank_clamped
    const int k0 = 3 * gq0 - rc0;
    const int k1 = 3 * gq1 - rc1;

    g_scratch[(b << LOGN) | n] = (gq0 & 0xFFFF) | (gq1 << 16);

    // block-level min reduction, then one atomicMin per block per dim
    int w0 = __reduce_min_sync(0xFFFFFFFFu, k0);
    int w1 = __reduce_min_sync(0xFFFFFFFFu, k1);
    __shared__ int sm0[8], sm1[8];
    const int warp = threadIdx.x >> 5;
    const int lane = threadIdx.x & 31;
    if (lane == 0) { sm0[warp] = w0; sm1[warp] = w1; }
    __syncthreads();
    if (threadIdx.x == 0) {
        int b0 = sm0[0], b1 = sm1[0];
        #pragma unroll
        for (int w = 1; w < 8; w++) { b0 = min(b0, sm0[w]); b1 = min(b1, sm1[w]); }
        atomicMin(&g_offmin[b * 2 + 0], b0);
        atomicMin(&g_offmin[b * 2 + 1], b1);
    }
}

// ceil(a/3) for any sign (C trunc-toward-zero division)
__device__ __forceinline__ int cdiv3(int a) {
    int q = a / 3;
    int r = a - q * 3;
    return q + (r > 0);
}

// ---------------------------------------------------------------------------
// Kernel C: splat features into the subsampled output grid
// ---------------------------------------------------------------------------
__global__ void __launch_bounds__(256) splat_kernel(const float* __restrict__ feat,
                                                    float* __restrict__ out) {
    const int b = blockIdx.x >> 8;
    const int n = ((blockIdx.x & 255) << 8) | threadIdx.x;

    const int packed = g_scratch[(b << LOGN) | n];
    const int gq0 = (int)(short)(packed & 0xFFFF);
    const int gq1 = packed >> 16;

    const int a0 = gq0 - cdiv3(g_offmin[b * 2 + 0]);
    const int a1 = gq1 - cdiv3(g_offmin[b * 2 + 1]);

    if ((unsigned)a0 < (unsigned)GRIDW && (unsigned)a1 < (unsigned)GRIDW) {
        const float* f = feat + ((size_t)b * 3) * NPTS + n;
        const float f0 = f[0];
        const float f1 = f[NPTS];
        const float f2 = f[2 * NPTS];
        float* o = out + ((size_t)((b << 14) + (a0 << 7) + a1)) * 3;
        atomicAdd(o + 0, f0);
        atomicAdd(o + 1, f1);
        atomicAdd(o + 2, f2);
    }
}

// ---------------------------------------------------------------------------
extern "C" void kernel_launch(void* const* d_in, const int* in_sizes, int n_in,
                              void* d_out, int out_size) {
    const float* pc1   = (const float*)d_in[0];
    const float* feat  = (const float*)d_in[1];
    const float* tmat  = (const float*)d_in[2];
    float* out = (float*)d_out;

    (void)in_sizes; (void)n_in; (void)out_size;

    zero_kernel<<<(OUT_ELEMS / 4 + 255) / 256, 256>>>((float4*)out);
    keys_kernel<<<BATCH * 256, 256>>>(pc1, tmat);
    splat_kernel<<<BATCH * 256, 256>>>(feat, out);
}

// round 6
// speedup vs baseline: 1.7283x; 1.7283x over previous
#include <cuda_runtime.h>
#include <cstdint>

// Problem constants
#define BATCH 32
#define NPTS  65536          // N
#define GRIDW 128            // S / D1 = 384 / 3
#define CELLS (GRIDW * GRIDW)                  // 16384 per batch
#define OUT_ELEMS (BATCH * CELLS * 3)          // 1,572,864 floats

// Scratch: packed per-point lattice coords (gq0 lo16, gq1 hi16)
__device__ int g_scratch[BATCH * NPTS];
// Per-batch key minima for dims 0,1 (memset to 0x7F7F7F7F each call)
__device__ int g_offmin[BATCH * 2];
// Padded accumulator: [b][cell][4] floats, 16B-aligned for float4 RED
__device__ __align__(16) float g_accum[BATCH * CELLS * 4];

// Separately-rounded dot3, left-associated ascending k (XLA loop-emitter order,
// NO fma contraction): fl(fl(fl(a0*b0) + fl(a1*b1)) + fl(a2*b2))
__device__ __forceinline__ float dot3_rn(float a0, float a1, float a2,
                                         float b0, float b1, float b2) {
    float s = __fmul_rn(a0, b0);
    s = __fadd_rn(s, __fmul_rn(a1, b1));
    s = __fadd_rn(s, __fmul_rn(a2, b2));
    return s;
}

// XLA:GPU-style f32 division: div.full.f32 (fast, <=2ulp, not IEEE-rounded)
__device__ __forceinline__ float fdiv_full(float a, float b) {
    float r;
    asm("div.full.f32 %0, %1, %2;" : "=f"(r) : "f"(a), "f"(b));
    return r;
}

// Per-point lattice computation (bit-identical to the passing R5 kernel).
// Returns packed (gq0 lo16 | gq1 hi16); k0/k1 are the per-point key minim cands.
__device__ __forceinline__ int point_coords(float p0, float p1, float p2,
                                            const float* __restrict__ tm,
                                            int& k0, int& k1) {
    const float e0 = dot3_rn(tm[0], tm[1], tm[2], p0, p1, p2);
    const float e1 = dot3_rn(tm[3], tm[4], tm[5], p0, p1, p2);
    const float e2 = dot3_rn(tm[6], tm[7], tm[8], p0, p1, p2);

    const float q0 = rintf(fdiv_full(e0, 3.0f));
    const float q1 = rintf(fdiv_full(e1, 3.0f));
    const float q2 = rintf(fdiv_full(e2, 3.0f));
    const float m0 = __fadd_rn(e0, -__fmul_rn(3.0f, q0));
    const float m1 = __fadd_rn(e1, -__fmul_rn(3.0f, q1));
    const float m2 = __fadd_rn(e2, -__fmul_rn(3.0f, q2));

    int r0 = (int)(m1 > m0) + (int)(m2 > m0);
    int r1 = (int)(m0 >= m1) + (int)(m2 > m1);

    int gq0 = (int)q0, gq1 = (int)q1, gq2 = (int)q2;
    const int rs = gq0 + gq1 + gq2;
    const int s  = (rs > 0) ? -1 : ((rs < 0) ? 1 : 0);

    const bool c0 = (rs > 0 && r0 >= 3 - rs) || (rs < 0 && r0 < -rs);
    const bool c1 = (rs > 0 && r1 >= 3 - rs) || (rs < 0 && r1 < -rs);
    gq0 += c0 ? s : 0;  r0 += (c0 ? 3 * s : 0) + rs;
    gq1 += c1 ? s : 0;  r1 += (c1 ? 3 * s : 0) + rs;

    const int rc0 = min(max(r0, 0), 2);
    const int rc1 = min(max(r1, 0), 2);

    k0 = 3 * gq0 - rc0;
    k1 = 3 * gq1 - rc1;
    return (gq0 & 0xFFFF) | (gq1 << 16);
}

// ---------------------------------------------------------------------------
// Kernel A: coords + offset-min + zero g_accum.   4 points per thread.
// grid = BATCH*64 blocks x 256 threads  (1024 pts/block)
// ---------------------------------------------------------------------------
__global__ void __launch_bounds__(256) keys_kernel(const float* __restrict__ pc1,
                                                   const float* __restrict__ tmat) {
    const int b  = blockIdx.x >> 6;
    const int n0 = ((blockIdx.x & 63) << 10) | (threadIdx.x << 2);
    const int gidx = blockIdx.x * 256 + threadIdx.x;      // 0 .. 524287

    // zero 16B of the accumulator (total = 524288 float4s, one per thread)
    reinterpret_cast<float4*>(g_accum)[gidx] = make_float4(0.f, 0.f, 0.f, 0.f);

    const float* pc = pc1 + ((size_t)b * 3) * NPTS;
    const float4 v0 = *reinterpret_cast<const float4*>(pc + n0);
    const float4 v1 = *reinterpret_cast<const float4*>(pc + NPTS + n0);
    const float4 v2 = *reinterpret_cast<const float4*>(pc + 2 * NPTS + n0);

    float tm[9];
    const float* tmg = tmat + b * 9;
    #pragma unroll
    for (int i = 0; i < 9; i++) tm[i] = __ldg(tmg + i);

    int4 packed;
    int k0a, k1a, k0b, k1b, k0c, k1c, k0d, k1d;
    packed.x = point_coords(v0.x, v1.x, v2.x, tm, k0a, k1a);
    packed.y = point_coords(v0.y, v1.y, v2.y, tm, k0b, k1b);
    packed.z = point_coords(v0.z, v1.z, v2.z, tm, k0c, k1c);
    packed.w = point_coords(v0.w, v1.w, v2.w, tm, k0d, k1d);

    reinterpret_cast<int4*>(g_scratch)[((size_t)b << 14) | (n0 >> 2)] = packed;

    const int k0 = min(min(k0a, k0b), min(k0c, k0d));
    const int k1 = min(min(k1a, k1b), min(k1c, k1d));

    int w0 = __reduce_min_sync(0xFFFFFFFFu, k0);
    int w1 = __reduce_min_sync(0xFFFFFFFFu, k1);
    __shared__ int sm0[8], sm1[8];
    const int warp = threadIdx.x >> 5;
    const int lane = threadIdx.x & 31;
    if (lane == 0) { sm0[warp] = w0; sm1[warp] = w1; }
    __syncthreads();
    if (threadIdx.x == 0) {
        int b0 = sm0[0], b1 = sm1[0];
        #pragma unroll
        for (int w = 1; w < 8; w++) { b0 = min(b0, sm0[w]); b1 = min(b1, sm1[w]); }
        atomicMin(&g_offmin[b * 2 + 0], b0);
        atomicMin(&g_offmin[b * 2 + 1], b1);
    }
}

// ceil(a/3) for any sign (C trunc-toward-zero division)
__device__ __forceinline__ int cdiv3(int a) {
    int q = a / 3;
    int r = a - q * 3;
    return q + (r > 0);
}

// ---------------------------------------------------------------------------
// Kernel B: splat — one float4 RED per point into the padded accumulator.
// 4 points per thread; grid = BATCH*64 x 256
// ---------------------------------------------------------------------------
__global__ void __launch_bounds__(256) splat_kernel(const float* __restrict__ feat) {
    const int b  = blockIdx.x >> 6;
    const int n0 = ((blockIdx.x & 63) << 10) | (threadIdx.x << 2);

    const int4 packed = reinterpret_cast<const int4*>(g_scratch)[((size_t)b << 14) | (n0 >> 2)];

    const int off0 = cdiv3(g_offmin[b * 2 + 0]);
    const int off1 = cdiv3(g_offmin[b * 2 + 1]);

    const float* f = feat + ((size_t)b * 3) * NPTS;
    const float4 f0 = *reinterpret_cast<const float4*>(f + n0);
    const float4 f1 = *reinterpret_cast<const float4*>(f + NPTS + n0);
    const float4 f2 = *reinterpret_cast<const float4*>(f + 2 * NPTS + n0);

    float4* acc = reinterpret_cast<float4*>(g_accum) + ((size_t)b << 14);

    const int pk[4] = {packed.x, packed.y, packed.z, packed.w};
    const float x0[4] = {f0.x, f0.y, f0.z, f0.w};
    const float x1[4] = {f1.x, f1.y, f1.z, f1.w};
    const float x2[4] = {f2.x, f2.y, f2.z, f2.w};

    #pragma unroll
    for (int i = 0; i < 4; i++) {
        const int a0 = ((int)(short)(pk[i] & 0xFFFF)) - off0;
        const int a1 = (pk[i] >> 16) - off1;
        if ((unsigned)a0 < (unsigned)GRIDW && (unsigned)a1 < (unsigned)GRIDW) {
            atomicAdd(acc + ((a0 << 7) | a1), make_float4(x0[i], x1[i], x2[i], 0.f));
        }
    }
}

// ---------------------------------------------------------------------------
// Kernel C: finalize — compact padded accum (4 f/cell) to output (3 f/cell).
// 4 cells per thread: read 64B, write 48B. grid = 512 x 256
// ---------------------------------------------------------------------------
__global__ void __launch_bounds__(256) finalize_kernel(float* __restrict__ out) {
    const int t = blockIdx.x * 256 + threadIdx.x;       // 0 .. 131071
    const float4* acc = reinterpret_cast<const float4*>(g_accum) + ((size_t)t << 2);
    const float4 c0 = acc[0];
    const float4 c1 = acc[1];
    const float4 c2 = acc[2];
    const float4 c3 = acc[3];
    float4* o = reinterpret_cast<float4*>(out + (size_t)t * 12);
    o[0] = make_float4(c0.x, c0.y, c0.z, c1.x);
    o[1] = make_float4(c1.y, c1.z, c2.x, c2.y);
    o[2] = make_float4(c2.z, c3.x, c3.y, c3.z);
}

// ---------------------------------------------------------------------------
extern "C" void kernel_launch(void* const* d_in, const int* in_sizes, int n_in,
                              void* d_out, int out_size) {
    const float* pc1   = (const float*)d_in[0];
    const float* feat  = (const float*)d_in[1];
    const float* tmat  = (const float*)d_in[2];
    float* out = (float*)d_out;

    (void)in_sizes; (void)n_in; (void)out_size;

    void* offmin_ptr = nullptr;
    cudaGetSymbolAddress(&offmin_ptr, g_offmin);
    cudaMemsetAsync(offmin_ptr, 0x7F, sizeof(int) * BATCH * 2);   // INT-large

    keys_kernel<<<BATCH * 64, 256>>>(pc1, tmat);
    splat_kernel<<<BATCH * 64, 256>>>(feat);
    finalize_kernel<<<512, 256>>>(out);
}

// round 7
// speedup vs baseline: 1.8631x; 1.0780x over previous
#include <cuda_runtime.h>
#include <cstdint>

// Problem constants
#define BATCH 32
#define NPTS  65536          // N
#define GRIDW 128            // S / D1 = 384 / 3
#define PADW  140            // padded accumulator width (>= 134 needed, margin)
#define PCELLS (PADW * PADW)                   // 19600
#define ACC_F4 (BATCH * PCELLS)                // 627,200 float4 cells (10.0 MB)

// Padded accumulator: [b][a0*140+a1] as float4
__device__ __align__(16) float g_accum[ACC_F4 * 4];
// Per-batch mins: [b][0]=k0min [b][1]=k1min [b][2]=floor(e0)min [b][3]=floor(e1)min
__device__ int g_mins[BATCH * 4];

// Separately-rounded dot3, left-associated ascending k (XLA loop-emitter order,
// NO fma contraction): fl(fl(fl(a0*b0) + fl(a1*b1)) + fl(a2*b2))
__device__ __forceinline__ float dot3_rn(float a0, float a1, float a2,
                                         float b0, float b1, float b2) {
    float s = __fmul_rn(a0, b0);
    s = __fadd_rn(s, __fmul_rn(a1, b1));
    s = __fadd_rn(s, __fmul_rn(a2, b2));
    return s;
}

// XLA:GPU-style f32 division: div.full.f32 (fast, <=2ulp, not IEEE-rounded)
__device__ __forceinline__ float fdiv_full(float a, float b) {
    float r;
    asm("div.full.f32 %0, %1, %2;" : "=f"(r) : "f"(a), "f"(b));
    return r;
}

__device__ __forceinline__ void block_min2_atomic(int v0, int v1, int* dst0, int* dst1) {
    int w0 = __reduce_min_sync(0xFFFFFFFFu, v0);
    int w1 = __reduce_min_sync(0xFFFFFFFFu, v1);
    __shared__ int sm0[8], sm1[8];
    const int warp = threadIdx.x >> 5;
    const int lane = threadIdx.x & 31;
    if (lane == 0) { sm0[warp] = w0; sm1[warp] = w1; }
    __syncthreads();
    if (threadIdx.x == 0) {
        int b0 = sm0[0], b1 = sm1[0];
        #pragma unroll
        for (int w = 1; w < 8; w++) { b0 = min(b0, sm0[w]); b1 = min(b1, sm1[w]); }
        atomicMin(dst0, b0);
        atomicMin(dst1, b1);
    }
}

// floor-div by 3 for any sign
__device__ __forceinline__ int fdiv3(int a) {
    int q = a / 3;                 // trunc toward zero
    return q - ((a - q * 3) < 0);  // adjust to floor
}
// ceil-div by 3 for any sign
__device__ __forceinline__ int cdiv3(int a) {
    int q = a / 3;
    return q + ((a - q * 3) > 0);
}
// anchor from floor(e)-min:  floor((min_floor_e - 8) / 3)
__device__ __forceinline__ int anchor_of(int efloor_min) {
    return fdiv3(efloor_min - 8);
}

// ---------------------------------------------------------------------------
// Kernel 1: anchor pass — min of floor(e0), floor(e1); zero the accumulator.
// grid = BATCH*64 x 256, 4 points/thread
// ---------------------------------------------------------------------------
__global__ void __launch_bounds__(256) anchor_kernel(const float* __restrict__ pc1,
                                                     const float* __restrict__ tmat) {
    const int b  = blockIdx.x >> 6;
    const int n0 = ((blockIdx.x & 63) << 10) | (threadIdx.x << 2);
    const int gidx = blockIdx.x * 256 + threadIdx.x;   // 0 .. 524287

    // zero the accumulator (627,200 float4s over 524,288 threads)
    float4* acc4 = reinterpret_cast<float4*>(g_accum);
    for (int i = gidx; i < ACC_F4; i += BATCH * 64 * 256)
        acc4[i] = make_float4(0.f, 0.f, 0.f, 0.f);

    const float* pc = pc1 + ((size_t)b * 3) * NPTS;
    const float4 v0 = *reinterpret_cast<const float4*>(pc + n0);
    const float4 v1 = *reinterpret_cast<const float4*>(pc + NPTS + n0);
    const float4 v2 = *reinterpret_cast<const float4*>(pc + 2 * NPTS + n0);

    const float* tm = tmat + b * 9;
    const float t00 = __ldg(tm + 0), t01 = __ldg(tm + 1), t02 = __ldg(tm + 2);
    const float t10 = __ldg(tm + 3), t11 = __ldg(tm + 4), t12 = __ldg(tm + 5);

    const float p0[4] = {v0.x, v0.y, v0.z, v0.w};
    const float p1[4] = {v1.x, v1.y, v1.z, v1.w};
    const float p2[4] = {v2.x, v2.y, v2.z, v2.w};

    int e0m = 0x7FFFFFFF, e1m = 0x7FFFFFFF;
    #pragma unroll
    for (int i = 0; i < 4; i++) {
        const float e0 = dot3_rn(t00, t01, t02, p0[i], p1[i], p2[i]);
        const float e1 = dot3_rn(t10, t11, t12, p0[i], p1[i], p2[i]);
        e0m = min(e0m, (int)floorf(e0));
        e1m = min(e1m, (int)floorf(e1));
    }
    block_min2_atomic(e0m, e1m, &g_mins[b * 4 + 2], &g_mins[b * 4 + 3]);
}

// ---------------------------------------------------------------------------
// Kernel 2: fused coords + exact k-min + splat into padded accumulator.
// grid = BATCH*64 x 256, 4 points/thread
// ---------------------------------------------------------------------------
__global__ void __launch_bounds__(256) splat_kernel(const float* __restrict__ pc1,
                                                    const float* __restrict__ feat,
                                                    const float* __restrict__ tmat) {
    const int b  = blockIdx.x >> 6;
    const int n0 = ((blockIdx.x & 63) << 10) | (threadIdx.x << 2);

    const int anch0 = anchor_of(g_mins[b * 4 + 2]);
    const int anch1 = anchor_of(g_mins[b * 4 + 3]);

    const float* pc = pc1 + ((size_t)b * 3) * NPTS;
    const float4 v0 = *reinterpret_cast<const float4*>(pc + n0);
    const float4 v1 = *reinterpret_cast<const float4*>(pc + NPTS + n0);
    const float4 v2 = *reinterpret_cast<const float4*>(pc + 2 * NPTS + n0);

    const float* f = feat + ((size_t)b * 3) * NPTS;
    const float4 f0 = *reinterpret_cast<const float4*>(f + n0);
    const float4 f1 = *reinterpret_cast<const float4*>(f + NPTS + n0);
    const float4 f2 = *reinterpret_cast<const float4*>(f + 2 * NPTS + n0);

    float tm[9];
    const float* tmg = tmat + b * 9;
    #pragma unroll
    for (int i = 0; i < 9; i++) tm[i] = __ldg(tmg + i);

    float4* acc = reinterpret_cast<float4*>(g_accum) + (size_t)b * PCELLS;

    const float p0[4] = {v0.x, v0.y, v0.z, v0.w};
    const float p1[4] = {v1.x, v1.y, v1.z, v1.w};
    const float p2[4] = {v2.x, v2.y, v2.z, v2.w};
    const float x0[4] = {f0.x, f0.y, f0.z, f0.w};
    const float x1[4] = {f1.x, f1.y, f1.z, f1.w};
    const float x2[4] = {f2.x, f2.y, f2.z, f2.w};

    int k0min = 0x7FFFFFFF, k1min = 0x7FFFFFFF;

    #pragma unroll
    for (int i = 0; i < 4; i++) {
        // ---- exact per-point lattice computation (bit-identical to R5/R6) ----
        const float e0 = dot3_rn(tm[0], tm[1], tm[2], p0[i], p1[i], p2[i]);
        const float e1 = dot3_rn(tm[3], tm[4], tm[5], p0[i], p1[i], p2[i]);
        const float e2 = dot3_rn(tm[6], tm[7], tm[8], p0[i], p1[i], p2[i]);

        const float q0 = rintf(fdiv_full(e0, 3.0f));
        const float q1 = rintf(fdiv_full(e1, 3.0f));
        const float q2 = rintf(fdiv_full(e2, 3.0f));
        const float m0 = __fadd_rn(e0, -__fmul_rn(3.0f, q0));
        const float m1 = __fadd_rn(e1, -__fmul_rn(3.0f, q1));
        const float m2 = __fadd_rn(e2, -__fmul_rn(3.0f, q2));

        int r0 = (int)(m1 > m0) + (int)(m2 > m0);
        int r1 = (int)(m0 >= m1) + (int)(m2 > m1);

        int gq0 = (int)q0, gq1 = (int)q1, gq2 = (int)q2;
        const int rs = gq0 + gq1 + gq2;
        const int s  = (rs > 0) ? -1 : ((rs < 0) ? 1 : 0);

        const bool c0 = (rs > 0 && r0 >= 3 - rs) || (rs < 0 && r0 < -rs);
        const bool c1 = (rs > 0 && r1 >= 3 - rs) || (rs < 0 && r1 < -rs);
        gq0 += c0 ? s : 0;  r0 += (c0 ? 3 * s : 0) + rs;
        gq1 += c1 ? s : 0;  r1 += (c1 ? 3 * s : 0) + rs;

        const int rc0 = min(max(r0, 0), 2);
        const int rc1 = min(max(r1, 0), 2);

        k0min = min(k0min, 3 * gq0 - rc0);
        k1min = min(k1min, 3 * gq1 - rc1);

        // ---- splat at anchored absolute coords (padding never read back) ----
        const int a0 = gq0 - anch0;
        const int a1 = gq1 - anch1;
        if ((unsigned)a0 < (unsigned)PADW && (unsigned)a1 < (unsigned)PADW) {
            atomicAdd(acc + (a0 * PADW + a1), make_float4(x0[i], x1[i], x2[i], 0.f));
        }
    }

    block_min2_atomic(k0min, k1min, &g_mins[b * 4 + 0], &g_mins[b * 4 + 1]);
}

// ---------------------------------------------------------------------------
// Kernel 3: finalize — gather the exact 128x128 window, write 3 floats/cell.
// grid = 512 x 256; 4 cells (one row-quad) per thread
// ---------------------------------------------------------------------------
__global__ void __launch_bounds__(256) finalize_kernel(float* __restrict__ out) {
    const int t = blockIdx.x * 256 + threadIdx.x;  // 0 .. 131071
    const int b = t >> 12;                         // 4096 threads per batch
    const int c = t & 4095;
    const int i = c >> 5;                          // row 0..127
    const int j = (c & 31) << 2;                   // col 0,4,..,124

    const int r0 = cdiv3(g_mins[b * 4 + 0]) - anchor_of(g_mins[b * 4 + 2]);
    const int r1 = cdiv3(g_mins[b * 4 + 1]) - anchor_of(g_mins[b * 4 + 3]);

    const float4* acc = reinterpret_cast<const float4*>(g_accum)
                      + (size_t)b * PCELLS + (r0 + i) * PADW + (r1 + j);
    const float4 c0 = acc[0];
    const float4 c1 = acc[1];
    const float4 c2 = acc[2];
    const float4 c3 = acc[3];

    float4* o = reinterpret_cast<float4*>(out + (size_t)t * 12);
    o[0] = make_float4(c0.x, c0.y, c0.z, c1.x);
    o[1] = make_float4(c1.y, c1.z, c2.x, c2.y);
    o[2] = make_float4(c2.z, c3.x, c3.y, c3.z);
}

// ---------------------------------------------------------------------------
extern "C" void kernel_launch(void* const* d_in, const int* in_sizes, int n_in,
                              void* d_out, int out_size) {
    const float* pc1   = (const float*)d_in[0];
    const float* feat  = (const float*)d_in[1];
    const float* tmat  = (const float*)d_in[2];
    float* out = (float*)d_out;

    (void)in_sizes; (void)n_in; (void)out_size;

    void* mins_ptr = nullptr;
    cudaGetSymbolAddress(&mins_ptr, g_mins);
    cudaMemsetAsync(mins_ptr, 0x7F, sizeof(int) * BATCH * 4);   // large positive ints

    anchor_kernel<<<BATCH * 64, 256>>>(pc1, tmat);
    splat_kernel<<<BATCH * 64, 256>>>(pc1, feat, tmat);
    finalize_kernel<<<512, 256>>>(out);
}